// round 1
// baseline (speedup 1.0000x reference)
#include <cuda_runtime.h>
#include <cstdint>

// Problem constants (match reference)
#define NN   25000   // nodes
#define NE   100000  // edges
#define HD   32      // hidden dim
#define NCL  8000    // cliques
#define NA   50000   // node2clique assignments
#define NEC  24000   // clique edges
#define EDIM 8       // edge emb dims (EEMB == CEE == 8)
#define NLAY 2

// ---------------- scratch (device globals; no dynamic allocation) -------------
__device__ float g_x[NN * HD];
__device__ float g_c[NCL * HD];
__device__ float g_h[NE * HD];                 // per-edge hidden (reused for clique edges)
__device__ float g_P[(size_t)NN * HD * HD];    // per-node precomputed contraction (102.4 MB)
__device__ float g_Q[NN * HD];                 // bias contraction
__device__ float g_T[HD * HD * HD];            // permuted w2
__device__ float g_agg[NN * HD];               // scatter accumulation buffer
__device__ float g_m[NN * HD];                 // projected features
__device__ int   g_deg_dst[NN];
__device__ int   g_deg_cdst[NCL];
__device__ int   g_deg_cid[NCL];
__device__ int   g_deg_nid[NN];

// ---------------- utility kernels ---------------------------------------------
__global__ void k_copy_f(const float* __restrict__ src, float* __restrict__ dst, int n) {
    int i = blockIdx.x * blockDim.x + threadIdx.x;
    if (i < n) dst[i] = src[i];
}

__global__ void k_zero_f(float* __restrict__ p, int n) {
    int i = blockIdx.x * blockDim.x + threadIdx.x;
    if (i < n) p[i] = 0.f;
}

__global__ void k_zero_i(int* __restrict__ p, int n) {
    int i = blockIdx.x * blockDim.x + threadIdx.x;
    if (i < n) p[i] = 0;
}

__global__ void k_count(const int* __restrict__ idx, int* __restrict__ deg, int n) {
    int i = blockIdx.x * blockDim.x + threadIdx.x;
    if (i < n) atomicAdd(&deg[idx[i]], 1);
}

// ---------------- edge MLP: h = relu(ef @ w1 + b1), warp per edge --------------
__global__ void k_edge_mlp(int nE, const float* __restrict__ ef,
                           const float* __restrict__ w1, const float* __restrict__ b1,
                           float* __restrict__ hout) {
    int e = (blockIdx.x * blockDim.x + threadIdx.x) >> 5;
    int lane = threadIdx.x & 31;
    if (e >= nE) return;
    float ev = (lane < EDIM) ? ef[(size_t)e * EDIM + lane] : 0.f;
    float acc = b1[lane];
#pragma unroll
    for (int j = 0; j < EDIM; j++)
        acc += __shfl_sync(0xffffffffu, ev, j) * w1[j * HD + lane];
    hout[(size_t)e * HD + lane] = fmaxf(acc, 0.f);
}

// ---------------- permute w2[k, i*H+o] -> T[i, k*H+o] --------------------------
__global__ void k_permT(const float* __restrict__ w2, float* __restrict__ T) {
    int tid = blockIdx.x * blockDim.x + threadIdx.x;
    if (tid >= HD * HD * HD) return;
    int o = tid & 31;
    int k = (tid >> 5) & 31;
    int i = tid >> 10;
    T[tid] = w2[k * (HD * HD) + i * HD + o];   // T index == i*1024 + k*32 + o
}

// ---------------- P = X @ T : [nrows x 32] @ [32 x 1024] -----------------------
// 128x128 tile per block, 256 threads, 8x8 per thread, K=32 (single tile load).
__global__ __launch_bounds__(256, 2)
void k_gemmP(const float* __restrict__ X, int nrows,
             const float* __restrict__ T, float* __restrict__ P) {
    __shared__ float As[HD][128];   // [k][row]
    __shared__ float Bs[HD][128];   // [k][col]
    int tid  = threadIdx.x;
    int row0 = blockIdx.x * 128;
    int col0 = blockIdx.y * 128;

    // load X tile (transposed into As)
    {
        int r = tid >> 3;        // 0..31
        int q = tid & 7;         // which float4 of the 32-wide row
        for (int rr = r; rr < 128; rr += 32) {
            int row = row0 + rr;
            float4 v = make_float4(0.f, 0.f, 0.f, 0.f);
            if (row < nrows) v = *(const float4*)(X + (size_t)row * HD + q * 4);
            As[q * 4 + 0][rr] = v.x;
            As[q * 4 + 1][rr] = v.y;
            As[q * 4 + 2][rr] = v.z;
            As[q * 4 + 3][rr] = v.w;
        }
    }
    // load T tile
    {
        int r = tid >> 5;        // 0..7
        int q = tid & 31;        // float4 col index
        for (int kk = r; kk < HD; kk += 8) {
            float4 v = *(const float4*)(T + kk * (HD * HD) + col0 + q * 4);
            *(float4*)&Bs[kk][q * 4] = v;
        }
    }
    __syncthreads();

    int tr = (tid >> 4) * 8;
    int tc = (tid & 15) * 8;
    float acc[8][8];
#pragma unroll
    for (int a = 0; a < 8; a++)
#pragma unroll
        for (int b = 0; b < 8; b++) acc[a][b] = 0.f;

#pragma unroll
    for (int k = 0; k < HD; k++) {
        float a[8], b[8];
        *(float4*)&a[0] = *(float4*)&As[k][tr];
        *(float4*)&a[4] = *(float4*)&As[k][tr + 4];
        *(float4*)&b[0] = *(float4*)&Bs[k][tc];
        *(float4*)&b[4] = *(float4*)&Bs[k][tc + 4];
#pragma unroll
        for (int i = 0; i < 8; i++)
#pragma unroll
            for (int j = 0; j < 8; j++)
                acc[i][j] += a[i] * b[j];
    }

#pragma unroll
    for (int i = 0; i < 8; i++) {
        int row = row0 + tr + i;
        if (row < nrows) {
            float* dst = P + (size_t)row * (HD * HD) + col0 + tc;
            *(float4*)(dst)     = make_float4(acc[i][0], acc[i][1], acc[i][2], acc[i][3]);
            *(float4*)(dst + 4) = make_float4(acc[i][4], acc[i][5], acc[i][6], acc[i][7]);
        }
    }
}

// ---------------- out = X @ W (+ b), warp per row ------------------------------
__global__ void k_linear(const float* __restrict__ X, const float* __restrict__ W,
                         const float* __restrict__ b, float* __restrict__ out, int nrows) {
    int r = (blockIdx.x * blockDim.x + threadIdx.x) >> 5;
    int lane = threadIdx.x & 31;
    if (r >= nrows) return;
    float xv = X[(size_t)r * HD + lane];
    float acc = b ? b[lane] : 0.f;
#pragma unroll
    for (int i = 0; i < HD; i++)
        acc += __shfl_sync(0xffffffffu, xv, i) * W[i * HD + lane];
    out[(size_t)r * HD + lane] = acc;
}

// ---------------- per-edge message + scatter-add, warp per edge ----------------
__global__ void k_edge_msg(int nE, const int* __restrict__ src, const int* __restrict__ dst,
                           const float* __restrict__ h, const float* __restrict__ P,
                           const float* __restrict__ Q, float* __restrict__ agg) {
    int e = (blockIdx.x * blockDim.x + threadIdx.x) >> 5;
    int lane = threadIdx.x & 31;
    if (e >= nE) return;
    int s = src[e];
    int d = dst[e];
    float hv = h[(size_t)e * HD + lane];
    const float* Pr = P + (size_t)s * (HD * HD);
    float acc = Q[(size_t)s * HD + lane];
#pragma unroll
    for (int k = 0; k < HD; k++)
        acc += __shfl_sync(0xffffffffu, hv, k) * Pr[k * HD + lane];
    atomicAdd(&agg[(size_t)d * HD + lane], acc);
}

// ---------------- nnconv epilogue: X = relu(agg/deg + X@rw + rb), in-place -----
__global__ void k_finalize(float* __restrict__ X, const float* __restrict__ agg,
                           const int* __restrict__ deg, const float* __restrict__ rw,
                           const float* __restrict__ rb, int nrows) {
    int r = (blockIdx.x * blockDim.x + threadIdx.x) >> 5;
    int lane = threadIdx.x & 31;
    if (r >= nrows) return;
    float xv = X[(size_t)r * HD + lane];
    float acc = rb[lane] + agg[(size_t)r * HD + lane] / fmaxf((float)deg[r], 1.f);
#pragma unroll
    for (int i = 0; i < HD; i++)
        acc += __shfl_sync(0xffffffffu, xv, i) * rw[i * HD + lane];
    X[(size_t)r * HD + lane] = fmaxf(acc, 0.f);
}

// ---------------- scatter m[from[a]] into agg[to[a]], warp per assignment ------
__global__ void k_scatter(int nA, const int* __restrict__ from, const int* __restrict__ to,
                          const float* __restrict__ m, float* __restrict__ agg) {
    int a = (blockIdx.x * blockDim.x + threadIdx.x) >> 5;
    int lane = threadIdx.x & 31;
    if (a >= nA) return;
    float v = m[(size_t)from[a] * HD + lane];
    atomicAdd(&agg[(size_t)to[a] * HD + lane], v);
}

// ---------------- X += agg/deg (mean residual), elementwise --------------------
__global__ void k_add_mean(float* __restrict__ X, const float* __restrict__ agg,
                           const int* __restrict__ deg, int nrows) {
    int i = blockIdx.x * blockDim.x + threadIdx.x;
    if (i >= nrows * HD) return;
    X[i] += agg[i] / fmaxf((float)deg[i / HD], 1.f);
}

// ---------------- output assembly: out = concat(x, c) --------------------------
__global__ void k_output(const float* __restrict__ x, const float* __restrict__ c,
                         float* __restrict__ out) {
    int i = blockIdx.x * blockDim.x + threadIdx.x;
    if (i < NN * HD) out[i] = x[i];
    else if (i < NN * HD + NCL * HD) out[i] = c[i - NN * HD];
}

// ================================================================================
static inline int cdiv(int a, int b) { return (a + b - 1) / b; }

extern "C" void kernel_launch(void* const* d_in, const int* in_sizes, int n_in,
                              void* d_out, int out_size) {
    // input pointers per metadata order
    const float* node_features   = (const float*)d_in[0];
    const int*   edge_index      = (const int*)d_in[1];
    const float* edge_features   = (const float*)d_in[2];
    const float* clique_features = (const float*)d_in[3];
    const int*   n2c_index       = (const int*)d_in[4];
    const int*   cedge_index     = (const int*)d_in[5];
    const float* cedge_features  = (const float*)d_in[6];
    const float* nn1_w  = (const float*)d_in[7];
    const float* nn1_b  = (const float*)d_in[8];
    const float* nn2_w  = (const float*)d_in[9];
    const float* nn2_b  = (const float*)d_in[10];
    const float* root_w = (const float*)d_in[11];
    const float* root_b = (const float*)d_in[12];
    const float* n2c_w  = (const float*)d_in[13];
    const float* n2c_b  = (const float*)d_in[14];
    const float* cnn1_w = (const float*)d_in[15];
    const float* cnn1_b = (const float*)d_in[16];
    const float* cnn2_w = (const float*)d_in[17];
    const float* cnn2_b = (const float*)d_in[18];
    const float* croot_w = (const float*)d_in[19];
    const float* croot_b = (const float*)d_in[20];
    const float* c2n_w  = (const float*)d_in[21];
    const float* c2n_b  = (const float*)d_in[22];
    float* out = (float*)d_out;

    const int* src  = edge_index;            // [E]
    const int* dst  = edge_index + NE;       // [E]
    const int* nid  = n2c_index;             // [A]
    const int* cid  = n2c_index + NA;        // [A]
    const int* csrc = cedge_index;           // [EC]
    const int* cdst = cedge_index + NEC;     // [EC]

    float *x, *c, *h, *P, *Q, *T, *agg, *m;
    int *deg_dst, *deg_cdst, *deg_cid, *deg_nid;
    cudaGetSymbolAddress((void**)&x, g_x);
    cudaGetSymbolAddress((void**)&c, g_c);
    cudaGetSymbolAddress((void**)&h, g_h);
    cudaGetSymbolAddress((void**)&P, g_P);
    cudaGetSymbolAddress((void**)&Q, g_Q);
    cudaGetSymbolAddress((void**)&T, g_T);
    cudaGetSymbolAddress((void**)&agg, g_agg);
    cudaGetSymbolAddress((void**)&m, g_m);
    cudaGetSymbolAddress((void**)&deg_dst, g_deg_dst);
    cudaGetSymbolAddress((void**)&deg_cdst, g_deg_cdst);
    cudaGetSymbolAddress((void**)&deg_cid, g_deg_cid);
    cudaGetSymbolAddress((void**)&deg_nid, g_deg_nid);

    const int TB = 256;

    // init state
    k_copy_f<<<cdiv(NN * HD, TB), TB>>>(node_features, x, NN * HD);
    k_copy_f<<<cdiv(NCL * HD, TB), TB>>>(clique_features, c, NCL * HD);

    // degrees (fixed index structure; recomputed each call for determinism)
    k_zero_i<<<cdiv(NN, TB), TB>>>(deg_dst, NN);
    k_zero_i<<<cdiv(NCL, TB), TB>>>(deg_cdst, NCL);
    k_zero_i<<<cdiv(NCL, TB), TB>>>(deg_cid, NCL);
    k_zero_i<<<cdiv(NN, TB), TB>>>(deg_nid, NN);
    k_count<<<cdiv(NE, TB), TB>>>(dst, deg_dst, NE);
    k_count<<<cdiv(NEC, TB), TB>>>(cdst, deg_cdst, NEC);
    k_count<<<cdiv(NA, TB), TB>>>(cid, deg_cid, NA);
    k_count<<<cdiv(NA, TB), TB>>>(nid, deg_nid, NA);

    for (int l = 0; l < NLAY; l++) {
        // ---- node NNConv: x = relu(nnconv(x, edges)) ----
        k_edge_mlp<<<cdiv(NE * 32, TB), TB>>>(NE, edge_features,
                                              nn1_w + l * EDIM * HD, nn1_b + l * HD, h);
        k_permT<<<cdiv(HD * HD * HD, TB), TB>>>(nn2_w + l * HD * HD * HD, T);
        {
            dim3 grid(cdiv(NN, 128), 8);
            k_gemmP<<<grid, 256>>>(x, NN, T, P);
        }
        k_linear<<<cdiv(NN * 32, TB), TB>>>(x, nn2_b + l * HD * HD, nullptr, Q, NN);
        k_zero_f<<<cdiv(NN * HD, TB), TB>>>(agg, NN * HD);
        k_edge_msg<<<cdiv(NE * 32, TB), TB>>>(NE, src, dst, h, P, Q, agg);
        k_finalize<<<cdiv(NN * 32, TB), TB>>>(x, agg, deg_dst,
                                              root_w + l * HD * HD, root_b + l * HD, NN);

        // ---- Node2Clique: c += segment_mean((x@W+b)[nid], cid) ----
        k_linear<<<cdiv(NN * 32, TB), TB>>>(x, n2c_w + l * HD * HD, n2c_b + l * HD, m, NN);
        k_zero_f<<<cdiv(NCL * HD, TB), TB>>>(agg, NCL * HD);
        k_scatter<<<cdiv(NA * 32, TB), TB>>>(NA, nid, cid, m, agg);
        k_add_mean<<<cdiv(NCL * HD, TB), TB>>>(c, agg, deg_cid, NCL);

        // ---- clique NNConv: c = relu(nnconv(c, clique edges)) ----
        k_edge_mlp<<<cdiv(NEC * 32, TB), TB>>>(NEC, cedge_features,
                                               cnn1_w + l * EDIM * HD, cnn1_b + l * HD, h);
        k_permT<<<cdiv(HD * HD * HD, TB), TB>>>(cnn2_w + l * HD * HD * HD, T);
        {
            dim3 grid(cdiv(NCL, 128), 8);
            k_gemmP<<<grid, 256>>>(c, NCL, T, P);
        }
        k_linear<<<cdiv(NCL * 32, TB), TB>>>(c, cnn2_b + l * HD * HD, nullptr, Q, NCL);
        k_zero_f<<<cdiv(NCL * HD, TB), TB>>>(agg, NCL * HD);
        k_edge_msg<<<cdiv(NEC * 32, TB), TB>>>(NEC, csrc, cdst, h, P, Q, agg);
        k_finalize<<<cdiv(NCL * 32, TB), TB>>>(c, agg, deg_cdst,
                                               croot_w + l * HD * HD, croot_b + l * HD, NCL);

        // ---- Clique2Node: x += segment_mean((c@W+b)[cid], nid) ----
        k_linear<<<cdiv(NCL * 32, TB), TB>>>(c, c2n_w + l * HD * HD, c2n_b + l * HD, m, NCL);
        k_zero_f<<<cdiv(NN * HD, TB), TB>>>(agg, NN * HD);
        k_scatter<<<cdiv(NA * 32, TB), TB>>>(NA, cid, nid, m, agg);
        k_add_mean<<<cdiv(NN * HD, TB), TB>>>(x, agg, deg_nid, NN);
    }

    // output: concat(x, c)
    k_output<<<cdiv(NN * HD + NCL * HD, TB), TB>>>(x, c, out);
}